// round 1
// baseline (speedup 1.0000x reference)
#include <cuda_runtime.h>
#include <cstdint>

#define FEAT   128
#define HID    128
#define HID2   64
#define BM     128
#define THREADS 256
#define PITCH  132     // h1 row pitch in floats (pad to kill bank conflicts on column reads)
#define MAXN   10000

// Per-node precomputed first-layer partials (allowed scratch: __device__ globals)
__device__ __align__(16) float g_Pdrug[MAXN * HID];
__device__ __align__(16) float g_Pdis [MAXN * HID];

__device__ __forceinline__ float gelu_exact(float x) {
    return 0.5f * x * (1.0f + erff(x * 0.70710678118654752440f));
}

// ---------------------------------------------------------------------------
// Precompute P = feat @ W1_slice  for both tables (blockIdx.y selects table).
// 32 nodes / block, 256 threads; thread = (tx in 0..31 -> 4 cols, ty in 0..7 -> 4 nodes)
// ---------------------------------------------------------------------------
__global__ __launch_bounds__(THREADS) void precompute_kernel(
    const float* __restrict__ drug, const float* __restrict__ dis,
    const float* __restrict__ W1, int n_drug, int n_dis)
{
    const int table = blockIdx.y;
    const int n = table ? n_dis : n_drug;
    const float* __restrict__ feat = table ? dis : drug;
    const float* __restrict__ w    = W1 + (table ? (size_t)FEAT * HID : 0);
    float* __restrict__ outp       = table ? g_Pdis : g_Pdrug;

    const int n0 = blockIdx.x * 32;
    if (n0 >= n) return;

    __shared__ float fs[32][FEAT];
    const int tid = threadIdx.x;
    for (int idx = tid; idx < 32 * FEAT; idx += THREADS) {
        int node = idx >> 7, k = idx & 127;
        fs[node][k] = (n0 + node < n) ? feat[(size_t)(n0 + node) * FEAT + k] : 0.0f;
    }
    __syncthreads();

    const int tx = tid & 31, ty = tid >> 5;
    float acc[4][4] = {};
    #pragma unroll 4
    for (int k = 0; k < FEAT; ++k) {
        float wv[4];
        #pragma unroll
        for (int c = 0; c < 4; ++c) wv[c] = w[(size_t)k * HID + tx + 32 * c];
        #pragma unroll
        for (int i = 0; i < 4; ++i) {
            float f = fs[ty * 4 + i][k];
            #pragma unroll
            for (int c = 0; c < 4; ++c) acc[i][c] = fmaf(f, wv[c], acc[i][c]);
        }
    }
    #pragma unroll
    for (int i = 0; i < 4; ++i) {
        int node = n0 + ty * 4 + i;
        if (node < n) {
            #pragma unroll
            for (int c = 0; c < 4; ++c)
                outp[(size_t)node * HID + tx + 32 * c] = acc[i][c];
        }
    }
}

// ---------------------------------------------------------------------------
// Fused per-edge kernel: 128 edges / block.
// Phase 1: z1 = P_drug[s] + P_dis[d] + b1 ; LN(128) ; GELU  -> smem h1 (pitch 132)
// Phase 2: h1[128x128] @ W2[128x64] with packed fma.rn.f32x2 (2 FMAs/instr)
// Phase 3: +b2 ; LN(64) ; GELU ; dot(W3)+b3 -> out   (register-resident)
// ---------------------------------------------------------------------------
extern __shared__ float smem[];

__global__ __launch_bounds__(THREADS, 2) void edge_kernel(
    const int* __restrict__ src, const int* __restrict__ dst,
    const float* __restrict__ b1, const float* __restrict__ g1, const float* __restrict__ be1,
    const float* __restrict__ W2, const float* __restrict__ b2,
    const float* __restrict__ g2, const float* __restrict__ be2,
    const float* __restrict__ W3, const float* __restrict__ b3,
    float* __restrict__ out, int E)
{
    float* h1s  = smem;                    // BM * PITCH
    float* w2s  = smem + BM * PITCH;       // HID * HID2  (offset 67584B, 16B aligned)
    float* w3s  = w2s + HID * HID2;
    float* b1s  = w3s + HID2;
    float* g1s  = b1s + HID;
    float* be1s = g1s + HID;
    float* b2s  = be1s + HID;
    float* g2s  = b2s + HID2;
    float* be2s = g2s + HID2;

    const int tid = threadIdx.x;
    for (int i = tid; i < HID * HID2; i += THREADS) w2s[i] = W2[i];
    if (tid < HID)  { b1s[tid] = b1[tid]; g1s[tid] = g1[tid]; be1s[tid] = be1[tid]; }
    if (tid < HID2) { w3s[tid] = W3[tid]; b2s[tid] = b2[tid]; g2s[tid] = g2[tid]; be2s[tid] = be2[tid]; }
    __syncthreads();

    const int e0 = blockIdx.x * BM;
    const int warp = tid >> 5, lane = tid & 31;

    // ---------------- Phase 1 ----------------
    for (int er = warp; er < BM; er += 8) {
        const int e = e0 + er;
        if (e < E) {
            const int s = src[e], d = dst[e];
            const float4 a  = reinterpret_cast<const float4*>(g_Pdrug + (size_t)s * HID)[lane];
            const float4 bq = reinterpret_cast<const float4*>(g_Pdis  + (size_t)d * HID)[lane];
            const float4 bb = reinterpret_cast<const float4*>(b1s)[lane];
            float v[4];
            v[0] = a.x + bq.x + bb.x;
            v[1] = a.y + bq.y + bb.y;
            v[2] = a.z + bq.z + bb.z;
            v[3] = a.w + bq.w + bb.w;
            float s1 = v[0] + v[1] + v[2] + v[3];
            float s2 = v[0]*v[0] + v[1]*v[1] + v[2]*v[2] + v[3]*v[3];
            #pragma unroll
            for (int m = 16; m > 0; m >>= 1) {
                s1 += __shfl_xor_sync(0xffffffffu, s1, m);
                s2 += __shfl_xor_sync(0xffffffffu, s2, m);
            }
            const float mu  = s1 * (1.0f / HID);
            const float var = s2 * (1.0f / HID) - mu * mu;
            const float rs  = rsqrtf(var + 1e-5f);
            const float4 gg = reinterpret_cast<const float4*>(g1s)[lane];
            const float4 ee = reinterpret_cast<const float4*>(be1s)[lane];
            float4 hv;
            hv.x = gelu_exact((v[0] - mu) * rs * gg.x + ee.x);
            hv.y = gelu_exact((v[1] - mu) * rs * gg.y + ee.y);
            hv.z = gelu_exact((v[2] - mu) * rs * gg.z + ee.z);
            hv.w = gelu_exact((v[3] - mu) * rs * gg.w + ee.w);
            reinterpret_cast<float4*>(h1s + er * PITCH)[lane] = hv;
        } else {
            float4 z = {0.f, 0.f, 0.f, 0.f};
            reinterpret_cast<float4*>(h1s + er * PITCH)[lane] = z;
        }
    }
    __syncthreads();

    // ---------------- Phase 2: GEMM2 with f32x2 packed FMA ----------------
    const int tx = tid & 7, ty = tid >> 3;     // tx -> 8 cols, ty -> 4 rows
    const int r0 = ty * 4, c0 = tx * 8;
    unsigned long long acc[4][4];
    #pragma unroll
    for (int i = 0; i < 4; ++i)
        #pragma unroll
        for (int p = 0; p < 4; ++p) acc[i][p] = 0ull;

    const ulonglong2* __restrict__ w2v = reinterpret_cast<const ulonglong2*>(w2s);

    #pragma unroll 4
    for (int k = 0; k < HID; ++k) {
        unsigned long long ap[4];
        #pragma unroll
        for (int i = 0; i < 4; ++i) {
            unsigned int au = __float_as_uint(h1s[(r0 + i) * PITCH + k]);
            asm("mov.b64 %0, {%1, %1};" : "=l"(ap[i]) : "r"(au));
        }
        const int vb = (k * HID2 + c0) >> 2;
        const ulonglong2 bw0 = w2v[vb];
        const ulonglong2 bw1 = w2v[vb + 1];
        const unsigned long long bw[4] = {bw0.x, bw0.y, bw1.x, bw1.y};
        #pragma unroll
        for (int i = 0; i < 4; ++i)
            #pragma unroll
            for (int p = 0; p < 4; ++p)
                asm("fma.rn.f32x2 %0, %1, %2, %0;" : "+l"(acc[i][p]) : "l"(ap[i]), "l"(bw[p]));
    }

    // ---------------- Phase 3 ----------------
    float w3r[8], g2r[8], be2r[8], b2r[8];
    #pragma unroll
    for (int cc = 0; cc < 8; ++cc) {
        w3r[cc] = w3s[c0 + cc]; g2r[cc] = g2s[c0 + cc];
        be2r[cc] = be2s[c0 + cc]; b2r[cc] = b2s[c0 + cc];
    }
    const float b3v = b3[0];

    #pragma unroll
    for (int i = 0; i < 4; ++i) {
        float z[8];
        #pragma unroll
        for (int p = 0; p < 4; ++p) {
            unsigned int lo, hi;
            asm("mov.b64 {%0, %1}, %2;" : "=r"(lo), "=r"(hi) : "l"(acc[i][p]));
            z[2 * p]     = __uint_as_float(lo) + b2r[2 * p];
            z[2 * p + 1] = __uint_as_float(hi) + b2r[2 * p + 1];
        }
        float s1 = 0.f, s2 = 0.f;
        #pragma unroll
        for (int cc = 0; cc < 8; ++cc) { s1 += z[cc]; s2 += z[cc] * z[cc]; }
        #pragma unroll
        for (int m = 4; m > 0; m >>= 1) {
            s1 += __shfl_xor_sync(0xffffffffu, s1, m);
            s2 += __shfl_xor_sync(0xffffffffu, s2, m);
        }
        const float mu  = s1 * (1.0f / HID2);
        const float var = s2 * (1.0f / HID2) - mu * mu;
        const float rs  = rsqrtf(var + 1e-5f);
        float dot = 0.f;
        #pragma unroll
        for (int cc = 0; cc < 8; ++cc) {
            float t = (z[cc] - mu) * rs * g2r[cc] + be2r[cc];
            dot = fmaf(gelu_exact(t), w3r[cc], dot);
        }
        #pragma unroll
        for (int m = 4; m > 0; m >>= 1)
            dot += __shfl_xor_sync(0xffffffffu, dot, m);
        const int e = e0 + r0 + i;
        if (tx == 0 && e < E) out[e] = dot + b3v;
    }
}

// ---------------------------------------------------------------------------
extern "C" void kernel_launch(void* const* d_in, const int* in_sizes, int n_in,
                              void* d_out, int out_size)
{
    const float* drug = (const float*)d_in[0];
    const float* dis  = (const float*)d_in[1];
    const int*   src  = (const int*)  d_in[2];
    const int*   dst  = (const int*)  d_in[3];
    const float* W1   = (const float*)d_in[4];
    const float* b1   = (const float*)d_in[5];
    const float* g1   = (const float*)d_in[6];
    const float* be1  = (const float*)d_in[7];
    const float* W2   = (const float*)d_in[8];
    const float* b2   = (const float*)d_in[9];
    const float* g2   = (const float*)d_in[10];
    const float* be2  = (const float*)d_in[11];
    const float* W3   = (const float*)d_in[12];
    const float* b3   = (const float*)d_in[13];
    float* out = (float*)d_out;

    const int n_drug = in_sizes[0] / FEAT;
    const int n_dis  = in_sizes[1] / FEAT;
    const int E      = in_sizes[2];

    const int nmax = n_drug > n_dis ? n_drug : n_dis;
    dim3 pgrid((nmax + 31) / 32, 2);
    precompute_kernel<<<pgrid, THREADS>>>(drug, dis, W1, n_drug, n_dis);

    const size_t SMEM_BYTES =
        (size_t)(BM * PITCH + HID * HID2 + HID2 + 3 * HID + 3 * HID2) * sizeof(float);
    cudaFuncSetAttribute(edge_kernel, cudaFuncAttributeMaxDynamicSharedMemorySize,
                         (int)SMEM_BYTES);
    const int blocks = (E + BM - 1) / BM;
    edge_kernel<<<blocks, THREADS, SMEM_BYTES>>>(
        src, dst, b1, g1, be1, W2, b2, g2, be2, W3, b3, out, E);
}